// round 1
// baseline (speedup 1.0000x reference)
#include <cuda_runtime.h>
#include <cuda_bf16.h>
#include <math.h>

// ---------------- constants ----------------
#define BATCH 4
#define HH 128
#define WW 128
#define HWP (HH*WW)          // 16384
#define KIDS 20

// ---------------- scratch (device globals; no allocation) ----------------
__device__ float g_buf1[BATCH * 256 * HWP];   // 67 MB
__device__ float g_buf2[BATCH * 128 * HWP];   // 33.5 MB
__device__ float g_buf3[BATCH * 64 * HWP];    // 16.8 MB
__device__ float g_mr[64];                    // mean/rstd pairs, max B*G=32
__device__ float g_partial[BATCH * 32 * KIDS * 64]; // pooled partial sums
__device__ float g_pcnt[BATCH * 32 * KIDS];         // pooled partial counts

// ---------------- conv as implicit GEMM ----------------
// A = weights [CO][CI*9] (OIHW contiguous), B = im2col [CI*9][B*H*W]
// N-tile = 128 = exactly one (b, y) row -> coalesced input loads.
template<int CI, int CO>
__global__ __launch_bounds__(256, 2)
void conv3x3_kernel(const float* __restrict__ in, const float* __restrict__ wgt,
                    const float* __restrict__ bias, float* __restrict__ out)
{
    constexpr int K = CI * 9;
    constexpr int BM = 128, BN = 128, BK = 8;
    __shared__ float As[BK][BM];
    __shared__ float Bs[BK][BN];

    const int tile = blockIdx.x;          // 0..511
    const int b = tile >> 7;              // /128
    const int y = tile & 127;
    const int m0 = blockIdx.y * BM;
    const int tid = threadIdx.x;
    const int ty = tid >> 4;              // 0..15
    const int tx = tid & 15;              // 0..15

    const float* inB = in + (size_t)b * CI * HWP;

    // A load mapping: one float4 per thread
    const int arow = tid >> 1;            // 0..127
    const int acol = (tid & 1) * 4;       // 0 or 4
    // B load mapping: 4 scalars per thread
    const int bcol = tid & 127;           // x coordinate
    const int brow0 = tid >> 7;           // 0..1

    float acc[8][8];
#pragma unroll
    for (int i = 0; i < 8; i++)
#pragma unroll
        for (int j = 0; j < 8; j++) acc[i][j] = 0.f;

    float4 aReg;
    float  bReg[4];

    auto loadA = [&](int k0) {
        if (m0 + arow < CO)
            aReg = *reinterpret_cast<const float4*>(wgt + (size_t)(m0 + arow) * K + k0 + acol);
        else
            aReg = make_float4(0.f, 0.f, 0.f, 0.f);
    };
    auto loadB = [&](int k0) {
#pragma unroll
        for (int i = 0; i < 4; i++) {
            int k = k0 + brow0 + 2 * i;
            int ci = k / 9;
            int rem = k - ci * 9;
            int dy = rem / 3;
            int dx = rem - dy * 3;
            int yy = y + dy - 1;
            int xx = bcol + dx - 1;
            float v = 0.f;
            if (yy >= 0 && yy < HH && xx >= 0 && xx < WW)
                v = inB[(ci * HH + yy) * WW + xx];
            bReg[i] = v;
        }
    };

    loadA(0);
    loadB(0);

    const int KT = K / BK;
    for (int kt = 0; kt < KT; kt++) {
        // stage registers -> smem
        As[acol + 0][arow] = aReg.x;
        As[acol + 1][arow] = aReg.y;
        As[acol + 2][arow] = aReg.z;
        As[acol + 3][arow] = aReg.w;
#pragma unroll
        for (int i = 0; i < 4; i++)
            Bs[brow0 + 2 * i][bcol] = bReg[i];
        __syncthreads();

        if (kt + 1 < KT) {      // prefetch next tile while computing
            loadA((kt + 1) * BK);
            loadB((kt + 1) * BK);
        }

#pragma unroll
        for (int kk = 0; kk < BK; kk++) {
            float a[8], bv[8];
            *reinterpret_cast<float4*>(a)      = *reinterpret_cast<const float4*>(&As[kk][ty * 8]);
            *reinterpret_cast<float4*>(a + 4)  = *reinterpret_cast<const float4*>(&As[kk][ty * 8 + 4]);
            *reinterpret_cast<float4*>(bv)     = *reinterpret_cast<const float4*>(&Bs[kk][tx * 8]);
            *reinterpret_cast<float4*>(bv + 4) = *reinterpret_cast<const float4*>(&Bs[kk][tx * 8 + 4]);
#pragma unroll
            for (int i = 0; i < 8; i++)
#pragma unroll
                for (int j = 0; j < 8; j++)
                    acc[i][j] = fmaf(a[i], bv[j], acc[i][j]);
        }
        __syncthreads();
    }

    // epilogue: add bias, store NCHW
    const int co0 = m0 + ty * 8;
    const int x0 = tx * 8;
#pragma unroll
    for (int i = 0; i < 8; i++) {
        int co = co0 + i;
        if (co < CO) {
            float bb_ = bias[co];
            float* dst = out + ((size_t)(b * CO + co) * HH + y) * WW + x0;
            float4 v0 = make_float4(acc[i][0] + bb_, acc[i][1] + bb_, acc[i][2] + bb_, acc[i][3] + bb_);
            float4 v1 = make_float4(acc[i][4] + bb_, acc[i][5] + bb_, acc[i][6] + bb_, acc[i][7] + bb_);
            *reinterpret_cast<float4*>(dst)     = v0;
            *reinterpret_cast<float4*>(dst + 4) = v1;
        }
    }
}

// ---------------- GroupNorm statistics ----------------
// one block per (b, g); writes mean & rstd
__global__ void gn_stats_kernel(const float* __restrict__ x, float* __restrict__ mr,
                                int C, int G)
{
    const int bg = blockIdx.x;
    const int g = bg % G;
    const int b = bg / G;
    const int Cg = C / G;
    const size_t base = ((size_t)b * C + (size_t)g * Cg) * HWP;
    const size_t n = (size_t)Cg * HWP;
    const float4* p = reinterpret_cast<const float4*>(x + base);
    const size_t n4 = n >> 2;

    float s = 0.f, ss = 0.f;
    for (size_t i = threadIdx.x; i < n4; i += blockDim.x) {
        float4 v = p[i];
        s  += v.x + v.y + v.z + v.w;
        ss += v.x * v.x + v.y * v.y + v.z * v.z + v.w * v.w;
    }
    __shared__ float sh_s[256], sh_ss[256];
    sh_s[threadIdx.x] = s;
    sh_ss[threadIdx.x] = ss;
    __syncthreads();
    for (int st = 128; st > 0; st >>= 1) {
        if ((int)threadIdx.x < st) {
            sh_s[threadIdx.x]  += sh_s[threadIdx.x + st];
            sh_ss[threadIdx.x] += sh_ss[threadIdx.x + st];
        }
        __syncthreads();
    }
    if (threadIdx.x == 0) {
        float inv_n = 1.f / (float)n;
        float mean = sh_s[0] * inv_n;
        float var = sh_ss[0] * inv_n - mean * mean;
        mr[bg * 2 + 0] = mean;
        mr[bg * 2 + 1] = rsqrtf(var + 1e-5f);
    }
}

// ---------------- GroupNorm apply + ReLU (in place) ----------------
__global__ void gn_apply_kernel(float* __restrict__ x, const float* __restrict__ mr,
                                const float* __restrict__ gw, const float* __restrict__ gb,
                                int C, int G)
{
    const int Cg = C / G;
    const size_t total4 = ((size_t)BATCH * C * HWP) >> 2;
    float4* p = reinterpret_cast<float4*>(x);
    for (size_t i4 = (size_t)blockIdx.x * blockDim.x + threadIdx.x; i4 < total4;
         i4 += (size_t)gridDim.x * blockDim.x) {
        size_t i = i4 << 2;
        int c = (int)((i / HWP) % C);
        int b = (int)(i / ((size_t)HWP * C));
        int g = c / Cg;
        float mean = mr[(b * G + g) * 2 + 0];
        float rstd = mr[(b * G + g) * 2 + 1];
        float scale = rstd * gw[c];
        float shift = gb[c] - mean * scale;
        float4 v = p[i4];
        v.x = fmaxf(fmaf(v.x, scale, shift), 0.f);
        v.y = fmaxf(fmaf(v.y, scale, shift), 0.f);
        v.z = fmaxf(fmaf(v.z, scale, shift), 0.f);
        v.w = fmaxf(fmaf(v.w, scale, shift), 0.f);
        p[i4] = v;
    }
}

// ---------------- masked segment pooling: partial accumulation ----------------
// grid = (32 chunks, BATCH); block 256; thread-per-pixel loops 64 channels.
__global__ void pool_acc_kernel(const float* __restrict__ h, const int* __restrict__ masks,
                                float* __restrict__ partial, float* __restrict__ pcnt)
{
    const int b = blockIdx.y;
    const int chunk = blockIdx.x;      // 0..31, 512 pixels each
    const int tid = threadIdx.x;

    __shared__ float s_sums[KIDS * 65];  // padded stride 65 (bank-conflict avoidance)
    __shared__ float s_cnt[KIDS];
    for (int i = tid; i < KIDS * 65; i += 256) s_sums[i] = 0.f;
    if (tid < KIDS) s_cnt[tid] = 0.f;
    __syncthreads();

    const float* hb = h + (size_t)b * 64 * HWP;
    const int* mb = masks + b * HWP;

    const int p0 = chunk * 512;
    for (int p = p0 + tid; p < p0 + 512; p += 256) {
        int k = mb[p] - 1;
        if (k >= 0) {
            atomicAdd(&s_cnt[k], 1.f);
#pragma unroll
            for (int c = 0; c < 64; c++)
                atomicAdd(&s_sums[k * 65 + c], hb[c * HWP + p]);
        }
    }
    __syncthreads();

    float* pb = partial + (size_t)(b * 32 + chunk) * (KIDS * 64);
    for (int i = tid; i < KIDS * 64; i += 256) {
        int k = i >> 6, c = i & 63;
        pb[i] = s_sums[k * 65 + c];
    }
    if (tid < KIDS) pcnt[(b * 32 + chunk) * KIDS + tid] = s_cnt[tid];
}

// ---------------- reduce partials + dense heads ----------------
// grid (BATCH, KIDS); block 64 (one thread per channel)
__global__ void heads_kernel(const float* __restrict__ partial, const float* __restrict__ pcnt,
                             const float* __restrict__ wb, const float* __restrict__ bb,
                             const float* __restrict__ wc, const float* __restrict__ bc,
                             float* __restrict__ out)
{
    const int b = blockIdx.x;
    const int k = blockIdx.y;
    const int c = threadIdx.x;   // 0..63

    float s = 0.f;
    for (int ch = 0; ch < 32; ch++)
        s += partial[(size_t)(b * 32 + ch) * (KIDS * 64) + k * 64 + c];
    float cnt = 0.f;
    for (int ch = 0; ch < 32; ch++)
        cnt += pcnt[(b * 32 + ch) * KIDS + k];
    float pooled = s / (cnt + 1e-6f);

    __shared__ float red[64];
#pragma unroll
    for (int o = 0; o < 7; o++) {
        red[c] = pooled * wb[o * 64 + c];
        __syncthreads();
        for (int st = 32; st > 0; st >>= 1) {
            if (c < st) red[c] += red[c + st];
            __syncthreads();
        }
        if (c == 0) out[(b * KIDS + k) * 7 + o] = red[0] + bb[o];
        __syncthreads();
    }
    red[c] = pooled * wc[c];
    __syncthreads();
    for (int st = 32; st > 0; st >>= 1) {
        if (c < st) red[c] += red[c + st];
        __syncthreads();
    }
    if (c == 0) {
        float z = red[0] + bc[0];
        out[BATCH * KIDS * 7 + b * KIDS + k] = 1.f / (1.f + expf(-z));
    }
}

// ---------------- launch ----------------
extern "C" void kernel_launch(void* const* d_in, const int* in_sizes, int n_in,
                              void* d_out, int out_size)
{
    const float* x    = (const float*)d_in[0];
    const int*   masks= (const int*)  d_in[1];
    const float* w1   = (const float*)d_in[2];
    const float* b1   = (const float*)d_in[3];
    const float* g1w  = (const float*)d_in[4];
    const float* g1b  = (const float*)d_in[5];
    const float* w2   = (const float*)d_in[6];
    const float* b2   = (const float*)d_in[7];
    const float* g2w  = (const float*)d_in[8];
    const float* g2b  = (const float*)d_in[9];
    const float* w3   = (const float*)d_in[10];
    const float* b3   = (const float*)d_in[11];
    const float* g3w  = (const float*)d_in[12];
    const float* g3b  = (const float*)d_in[13];
    const float* wb   = (const float*)d_in[14];
    const float* bb   = (const float*)d_in[15];
    const float* wc   = (const float*)d_in[16];
    const float* bc   = (const float*)d_in[17];
    float* out = (float*)d_out;

    float *buf1, *buf2, *buf3, *mr, *partial, *pcnt;
    cudaGetSymbolAddress((void**)&buf1, g_buf1);
    cudaGetSymbolAddress((void**)&buf2, g_buf2);
    cudaGetSymbolAddress((void**)&buf3, g_buf3);
    cudaGetSymbolAddress((void**)&mr, g_mr);
    cudaGetSymbolAddress((void**)&partial, g_partial);
    cudaGetSymbolAddress((void**)&pcnt, g_pcnt);

    // layer 1: 512 -> 256, GN(8) + relu
    conv3x3_kernel<512, 256><<<dim3(512, 2), 256>>>(x, w1, b1, buf1);
    gn_stats_kernel<<<32, 256>>>(buf1, mr, 256, 8);
    gn_apply_kernel<<<4096, 256>>>(buf1, mr, g1w, g1b, 256, 8);

    // layer 2: 256 -> 128, GN(4) + relu
    conv3x3_kernel<256, 128><<<dim3(512, 1), 256>>>(buf1, w2, b2, buf2);
    gn_stats_kernel<<<16, 256>>>(buf2, mr, 128, 4);
    gn_apply_kernel<<<2048, 256>>>(buf2, mr, g2w, g2b, 128, 4);

    // layer 3: 128 -> 64, GN(4) + relu
    conv3x3_kernel<128, 64><<<dim3(512, 1), 256>>>(buf2, w3, b3, buf3);
    gn_stats_kernel<<<16, 256>>>(buf3, mr, 64, 4);
    gn_apply_kernel<<<1024, 256>>>(buf3, mr, g3w, g3b, 64, 4);

    // masked segment-mean pooling + heads
    pool_acc_kernel<<<dim3(32, BATCH), 256>>>(buf3, masks, partial, pcnt);
    heads_kernel<<<dim3(BATCH, KIDS), 64>>>(partial, pcnt, wb, bb, wc, bc, out);
}

// round 4
// speedup vs baseline: 2.0860x; 2.0860x over previous
#include <cuda_runtime.h>
#include <cstdint>
#include <math.h>

#define HH 128
#define WW 128
#define HWP 16384
#define BATCH 4
#define KIDS 20

// ---------------- scratch (device globals; no allocation) ----------------
__device__ float g_buf1[BATCH * 256 * HWP];   // 67 MB
__device__ float g_buf2[BATCH * 128 * HWP];   // 33.5 MB
__device__ float g_buf3[BATCH * 64 * HWP];    // 16.8 MB
__device__ float g_mr[64];                    // mean/rstd pairs
__device__ float g_gnpart[4096];              // GN partial sums
__device__ float g_partial[BATCH * 32 * KIDS * 64];
__device__ float g_pcnt[BATCH * 32 * KIDS];

// ---------------- tf32 helpers ----------------
__device__ __forceinline__ uint32_t f2tf32(float x) {
    uint32_t r;
    asm("cvt.rna.tf32.f32 %0, %1;" : "=r"(r) : "f"(x));
    return r;
}
__device__ __forceinline__ void mma_tf32(float* c, uint32_t a0, uint32_t a1,
                                         uint32_t a2, uint32_t a3,
                                         uint32_t b0, uint32_t b1) {
    asm volatile("mma.sync.aligned.m16n8k8.row.col.f32.tf32.tf32.f32 "
                 "{%0,%1,%2,%3}, {%4,%5,%6,%7}, {%8,%9}, {%0,%1,%2,%3};"
                 : "+f"(c[0]), "+f"(c[1]), "+f"(c[2]), "+f"(c[3])
                 : "r"(a0), "r"(a1), "r"(a2), "r"(a3), "r"(b0), "r"(b1));
}

// ---------------- conv as tf32 mma.sync implicit GEMM ----------------
// A = weights [CO][K=CI*9] (OIHW flattened), B = im2col [128 px][K].
// K staged in chunks of 32 with position permutation pos(k) = (k%4)*8 + k/4
// so each m16n8k8 fragment is one aligned lds.64. Row stride 34 floats.
// GN+ReLU of the previous layer fused into B staging.
template<int CI, int CO, bool GN>
__global__ __launch_bounds__(256)
void conv_mma_kernel(const float* __restrict__ in, const float* __restrict__ wgt,
                     const float* __restrict__ bias, float* __restrict__ out,
                     const float* __restrict__ mr, const float* __restrict__ gw,
                     const float* __restrict__ gb, int Gin)
{
    constexpr int K = CI * 9;
    constexpr int NCHUNK = K / 32;
    constexpr int M = (CO < 128) ? CO : 128;  // M tile (rows of A staged)
    constexpr int MFRAG = M / 32;             // 16-row frags per warp (M/2/16)
    constexpr int SB = 34;                    // smem row stride in floats

    extern __shared__ char smem[];
    float* As = reinterpret_cast<float*>(smem);                   // [M][SB]
    float* Bs = As + M * SB;                                      // [128][SB]
    float* scp = Bs + 128 * SB;                                   // GN scale [CI]
    float* shp = scp + (GN ? CI : 0);                             // GN shift [CI]

    const int tile = blockIdx.x;
    const int b = tile >> 7;
    const int y = tile & 127;
    const int m0 = blockIdx.y * M;
    const int tid = threadIdx.x;
    const int w = tid >> 5;
    const int lane = tid & 31;
    const int g = lane >> 2;      // 0..7
    const int q = lane & 3;       // 0..3
    const int warpM = w >> 2;     // 0..1
    const int warpN = w & 3;      // 0..3
    const int m0w = warpM * (M / 2);
    const int n0w = warpN * 32;

    if (GN) {
        const int CPG = CI / Gin;
        for (int c = tid; c < CI; c += 256) {
            int gi = c / CPG;
            float mean = mr[(b * Gin + gi) * 2 + 0];
            float rstd = mr[(b * Gin + gi) * 2 + 1];
            float s = rstd * gw[c];
            scp[c] = s;
            shp[c] = gb[c] - mean * s;
        }
    }

    const float* inB = in + (size_t)b * CI * HWP;
    const int px = tid & 127;
    const int khalf = tid >> 7;

    float acc[MFRAG][4][4];
#pragma unroll
    for (int mi = 0; mi < MFRAG; mi++)
#pragma unroll
        for (int ni = 0; ni < 4; ni++)
#pragma unroll
            for (int j = 0; j < 4; j++) acc[mi][ni][j] = 0.f;

    for (int chunk = 0; chunk < NCHUNK; chunk++) {
        const int kbase = chunk * 32;
        __syncthreads();     // previous compute done before overwrite

        // ---- stage A (weights) with k-position permutation
        for (int idx = tid; idx < M * 8; idx += 256) {
            int row = idx >> 3;
            int c4 = (idx & 7) * 4;
            float4 v = *reinterpret_cast<const float4*>(
                wgt + (size_t)(m0 + row) * K + kbase + c4);
            float* dst = As + row * SB + (c4 >> 2);
            dst[0]  = __uint_as_float(f2tf32(v.x));
            dst[8]  = __uint_as_float(f2tf32(v.y));
            dst[16] = __uint_as_float(f2tf32(v.z));
            dst[24] = __uint_as_float(f2tf32(v.w));
        }
        // ---- stage B (im2col, GN+ReLU fused) with permutation
#pragma unroll
        for (int j = 0; j < 16; j++) {
            int kk = khalf * 16 + j;
            int k = kbase + kk;
            int ci = k / 9;
            int t9 = k - ci * 9;
            int dy = t9 / 3;
            int dx = t9 - dy * 3;
            int yy = y + dy - 1;
            int xx = px + dx - 1;
            float v = 0.f;
            if ((unsigned)yy < 128u && (unsigned)xx < 128u) {
                v = inB[(ci * HH + yy) * WW + xx];
                if (GN) v = fmaxf(fmaf(v, scp[ci], shp[ci]), 0.f);
            }
            Bs[px * SB + (kk & 3) * 8 + (kk >> 2)] = __uint_as_float(f2tf32(v));
        }
        __syncthreads();

        // ---- compute: 4 k-steps of m16n8k8
#pragma unroll
        for (int ks = 0; ks < 4; ks++) {
            uint32_t af[MFRAG][4];
#pragma unroll
            for (int mi = 0; mi < MFRAG; mi++) {
                int row = m0w + mi * 16 + g;
                float2 lo = *reinterpret_cast<const float2*>(As + row * SB + q * 8 + 2 * ks);
                float2 hi = *reinterpret_cast<const float2*>(As + (row + 8) * SB + q * 8 + 2 * ks);
                af[mi][0] = __float_as_uint(lo.x);
                af[mi][1] = __float_as_uint(hi.x);
                af[mi][2] = __float_as_uint(lo.y);
                af[mi][3] = __float_as_uint(hi.y);
            }
#pragma unroll
            for (int ni = 0; ni < 4; ni++) {
                int pxn = n0w + ni * 8 + g;
                float2 vb = *reinterpret_cast<const float2*>(Bs + pxn * SB + q * 8 + 2 * ks);
                uint32_t b0 = __float_as_uint(vb.x);
                uint32_t b1 = __float_as_uint(vb.y);
#pragma unroll
                for (int mi = 0; mi < MFRAG; mi++)
                    mma_tf32(acc[mi][ni], af[mi][0], af[mi][1], af[mi][2], af[mi][3], b0, b1);
            }
        }
    }

    // ---- epilogue: +bias, store NCHW as float2 pairs
#pragma unroll
    for (int mi = 0; mi < MFRAG; mi++) {
        int colo = m0 + m0w + mi * 16 + g;
        int cohi = colo + 8;
        float blo = bias[colo];
        float bhi = bias[cohi];
        float* dlo = out + (((size_t)(b * CO + colo)) * HH + y) * WW;
        float* dhi = out + (((size_t)(b * CO + cohi)) * HH + y) * WW;
#pragma unroll
        for (int ni = 0; ni < 4; ni++) {
            int x0 = n0w + ni * 8 + 2 * q;
            float2 v0 = make_float2(acc[mi][ni][0] + blo, acc[mi][ni][1] + blo);
            float2 v1 = make_float2(acc[mi][ni][2] + bhi, acc[mi][ni][3] + bhi);
            *reinterpret_cast<float2*>(dlo + x0) = v0;
            *reinterpret_cast<float2*>(dhi + x0) = v1;
        }
    }
}

// ---------------- GroupNorm statistics: partial pass ----------------
__global__ void gn_part_kernel(const float* __restrict__ x, float* __restrict__ part,
                               int Cg, int SL)
{
    const int bg = blockIdx.x / SL;
    const int sl = blockIdx.x % SL;
    const size_t n = (size_t)Cg * HWP;
    const size_t cn = n / SL;
    const float4* p = reinterpret_cast<const float4*>(x + (size_t)bg * n + (size_t)sl * cn);
    const int n4 = (int)(cn >> 2);

    float s = 0.f, ss = 0.f;
    for (int i = threadIdx.x; i < n4; i += 256) {
        float4 v = p[i];
        s  += v.x + v.y + v.z + v.w;
        ss += v.x * v.x + v.y * v.y + v.z * v.z + v.w * v.w;
    }
    __shared__ float sh_s[256], sh_ss[256];
    sh_s[threadIdx.x] = s;
    sh_ss[threadIdx.x] = ss;
    __syncthreads();
    for (int st = 128; st > 0; st >>= 1) {
        if ((int)threadIdx.x < st) {
            sh_s[threadIdx.x]  += sh_s[threadIdx.x + st];
            sh_ss[threadIdx.x] += sh_ss[threadIdx.x + st];
        }
        __syncthreads();
    }
    if (threadIdx.x == 0) {
        part[blockIdx.x * 2 + 0] = sh_s[0];
        part[blockIdx.x * 2 + 1] = sh_ss[0];
    }
}

// ---------------- GroupNorm statistics: final reduce ----------------
__global__ void gn_final_kernel(const float* __restrict__ part, float* __restrict__ mr,
                                int SL, float inv_n)
{
    const int bg = threadIdx.x;
    float s = 0.f, ss = 0.f;
    for (int i = 0; i < SL; i++) {
        s  += part[(bg * SL + i) * 2 + 0];
        ss += part[(bg * SL + i) * 2 + 1];
    }
    float mean = s * inv_n;
    float var = ss * inv_n - mean * mean;
    mr[bg * 2 + 0] = mean;
    mr[bg * 2 + 1] = rsqrtf(var + 1e-5f);
}

// ---------------- masked segment pooling (GN3+ReLU fused at read) ----------------
__global__ void pool_acc_kernel(const float* __restrict__ h, const int* __restrict__ masks,
                                const float* __restrict__ mr, const float* __restrict__ gw,
                                const float* __restrict__ gb,
                                float* __restrict__ partial, float* __restrict__ pcnt)
{
    const int b = blockIdx.y;
    const int chunk = blockIdx.x;
    const int tid = threadIdx.x;

    __shared__ float s_sums[KIDS * 65];
    __shared__ float s_cnt[KIDS];
    __shared__ float sc[64], sh[64];
    for (int i = tid; i < KIDS * 65; i += 256) s_sums[i] = 0.f;
    if (tid < KIDS) s_cnt[tid] = 0.f;
    if (tid < 64) {
        int g = tid >> 4;
        float mean = mr[(b * 4 + g) * 2 + 0];
        float rstd = mr[(b * 4 + g) * 2 + 1];
        float s = rstd * gw[tid];
        sc[tid] = s;
        sh[tid] = gb[tid] - mean * s;
    }
    __syncthreads();

    const float* hb = h + (size_t)b * 64 * HWP;
    const int* mb = masks + b * HWP;

    const int p0 = chunk * 512;
    for (int p = p0 + tid; p < p0 + 512; p += 256) {
        int k = mb[p] - 1;
        if (k >= 0) {
            atomicAdd(&s_cnt[k], 1.f);
#pragma unroll
            for (int c = 0; c < 64; c++) {
                float v = fmaxf(fmaf(hb[c * HWP + p], sc[c], sh[c]), 0.f);
                atomicAdd(&s_sums[k * 65 + c], v);
            }
        }
    }
    __syncthreads();

    float* pb = partial + (size_t)(b * 32 + chunk) * (KIDS * 64);
    for (int i = tid; i < KIDS * 64; i += 256) {
        int k = i >> 6, c = i & 63;
        pb[i] = s_sums[k * 65 + c];
    }
    if (tid < KIDS) pcnt[(b * 32 + chunk) * KIDS + tid] = s_cnt[tid];
}

// ---------------- reduce partials + dense heads ----------------
__global__ void heads_kernel(const float* __restrict__ partial, const float* __restrict__ pcnt,
                             const float* __restrict__ wb, const float* __restrict__ bb,
                             const float* __restrict__ wc, const float* __restrict__ bc,
                             float* __restrict__ out)
{
    const int b = blockIdx.x;
    const int k = blockIdx.y;
    const int c = threadIdx.x;

    float s = 0.f;
    for (int ch = 0; ch < 32; ch++)
        s += partial[(size_t)(b * 32 + ch) * (KIDS * 64) + k * 64 + c];
    float cnt = 0.f;
    for (int ch = 0; ch < 32; ch++)
        cnt += pcnt[(b * 32 + ch) * KIDS + k];
    float pooled = s / (cnt + 1e-6f);

    __shared__ float red[64];
#pragma unroll
    for (int o = 0; o < 7; o++) {
        red[c] = pooled * wb[o * 64 + c];
        __syncthreads();
        for (int st = 32; st > 0; st >>= 1) {
            if (c < st) red[c] += red[c + st];
            __syncthreads();
        }
        if (c == 0) out[(b * KIDS + k) * 7 + o] = red[0] + bb[o];
        __syncthreads();
    }
    red[c] = pooled * wc[c];
    __syncthreads();
    for (int st = 32; st > 0; st >>= 1) {
        if (c < st) red[c] += red[c + st];
        __syncthreads();
    }
    if (c == 0) {
        float z = red[0] + bc[0];
        out[BATCH * KIDS * 7 + b * KIDS + k] = 1.f / (1.f + expf(-z));
    }
}

// ---------------- launch ----------------
extern "C" void kernel_launch(void* const* d_in, const int* in_sizes, int n_in,
                              void* d_out, int out_size)
{
    const float* x    = (const float*)d_in[0];
    const int*   masks= (const int*)  d_in[1];
    const float* w1   = (const float*)d_in[2];
    const float* b1   = (const float*)d_in[3];
    const float* g1w  = (const float*)d_in[4];
    const float* g1b  = (const float*)d_in[5];
    const float* w2   = (const float*)d_in[6];
    const float* b2   = (const float*)d_in[7];
    const float* g2w  = (const float*)d_in[8];
    const float* g2b  = (const float*)d_in[9];
    const float* w3   = (const float*)d_in[10];
    const float* b3   = (const float*)d_in[11];
    const float* g3w  = (const float*)d_in[12];
    const float* g3b  = (const float*)d_in[13];
    const float* wb   = (const float*)d_in[14];
    const float* bb   = (const float*)d_in[15];
    const float* wc   = (const float*)d_in[16];
    const float* bc   = (const float*)d_in[17];
    float* out = (float*)d_out;

    float *buf1, *buf2, *buf3, *mr, *gnpart, *partial, *pcnt;
    cudaGetSymbolAddress((void**)&buf1, g_buf1);
    cudaGetSymbolAddress((void**)&buf2, g_buf2);
    cudaGetSymbolAddress((void**)&buf3, g_buf3);
    cudaGetSymbolAddress((void**)&mr, g_mr);
    cudaGetSymbolAddress((void**)&gnpart, g_gnpart);
    cudaGetSymbolAddress((void**)&partial, g_partial);
    cudaGetSymbolAddress((void**)&pcnt, g_pcnt);

    // dynamic smem: (M + 128) * 34 * 4 + GN arrays
    const int SM1 = (128 + 128) * 34 * 4;                 // 34816
    const int SM2 = (128 + 128) * 34 * 4 + 2 * 256 * 4;   // 36864
    const int SM3 = (64 + 128) * 34 * 4 + 2 * 128 * 4;    // 27136

    // layer 1: 512 -> 256
    conv_mma_kernel<512, 256, false><<<dim3(512, 2), 256, SM1>>>(
        x, w1, b1, buf1, nullptr, nullptr, nullptr, 0);
    gn_part_kernel<<<32 * 16, 256>>>(buf1, gnpart, 32, 16);
    gn_final_kernel<<<1, 32>>>(gnpart, mr, 16, 1.f / 524288.f);

    // layer 2: 256 -> 128 (GN1+ReLU fused into B staging)
    conv_mma_kernel<256, 128, true><<<dim3(512, 1), 256, SM2>>>(
        buf1, w2, b2, buf2, mr, g1w, g1b, 8);
    gn_part_kernel<<<16 * 32, 256>>>(buf2, gnpart, 32, 32);
    gn_final_kernel<<<1, 16>>>(gnpart, mr, 32, 1.f / 524288.f);

    // layer 3: 128 -> 64 (GN2+ReLU fused into B staging)
    conv_mma_kernel<128, 64, true><<<dim3(512, 1), 256, SM3>>>(
        buf2, w3, b3, buf3, mr, g2w, g2b, 4);
    gn_part_kernel<<<16 * 32, 256>>>(buf3, gnpart, 16, 32);
    gn_final_kernel<<<1, 16>>>(gnpart, mr, 32, 1.f / 262144.f);

    // pooling (GN3+ReLU fused at read) + heads
    pool_acc_kernel<<<dim3(32, BATCH), 256>>>(buf3, masks, mr, g3w, g3b, partial, pcnt);
    heads_kernel<<<dim3(BATCH, KIDS), 64>>>(partial, pcnt, wb, bb, wc, bc, out);
}